// round 12
// baseline (speedup 1.0000x reference)
#include <cuda_runtime.h>
#include <cuda_bf16.h>
#include <cuda_fp16.h>
#include <cstdint>

// ---------------------------------------------------------------------------
// MHConvAttention  (B=16, C=128, H=W=64, NH=8, HD=16, WIN=5, OUT=512)
// Round 12: qkv GEMM with fp16 accumulators @ 3 CTAs/SM; ECA folded into wprep
// ---------------------------------------------------------------------------
#define Bn   16
#define Cc   128
#define NHh  8
#define HDd  16
#define HW   4096
#define OUTC 512

__device__ __half g_s_h  [(size_t)Bn * Cc * HW];         // CPE output (fp16)
__device__ __half g_src_h[(size_t)Bn * Cc * HW];         // src (fp16)
__device__ __half g_r1_h [(size_t)Bn * Cc * HW];         // result1 (fp16)
__device__ __half g_qkv_h[(size_t)Bn * 3 * Cc * HW];     // q|k|v (fp16)
__device__ float  g_pool [Bn * Cc];
__device__ __half g_wcat_h[(size_t)Bn * OUTC * 256];     // [W1 | W2*ca(b)] fp16
__device__ __half g_qkvw_h[384 * 128];                   // qkv_w fp16
__device__ float  g_lpart[4][Bn * NHh * 256];
__device__ float  g_kps  [4][Bn * NHh * 16];

// ---------------------------------------------------------------------------
// helpers
// ---------------------------------------------------------------------------
__device__ __forceinline__ void mma16(float* c, const uint32_t* a, const uint32_t* b) {
    asm volatile(
        "mma.sync.aligned.m16n8k16.row.col.f32.f16.f16.f32 "
        "{%0,%1,%2,%3},{%4,%5,%6,%7},{%8,%9},{%0,%1,%2,%3};"
        : "+f"(c[0]), "+f"(c[1]), "+f"(c[2]), "+f"(c[3])
        : "r"(a[0]), "r"(a[1]), "r"(a[2]), "r"(a[3]), "r"(b[0]), "r"(b[1]));
}
__device__ __forceinline__ void mma16h(uint32_t* c, const uint32_t* a, const uint32_t* b) {
    asm volatile(
        "mma.sync.aligned.m16n8k16.row.col.f16.f16.f16.f16 "
        "{%0,%1},{%2,%3,%4,%5},{%6,%7},{%0,%1};"
        : "+r"(c[0]), "+r"(c[1])
        : "r"(a[0]), "r"(a[1]), "r"(a[2]), "r"(a[3]), "r"(b[0]), "r"(b[1]));
}
__device__ __forceinline__ void ldsm4(uint32_t& r0, uint32_t& r1, uint32_t& r2, uint32_t& r3,
                                      uint32_t addr) {
    asm volatile("ldmatrix.sync.aligned.m8n8.x4.shared.b16 {%0,%1,%2,%3}, [%4];"
                 : "=r"(r0), "=r"(r1), "=r"(r2), "=r"(r3) : "r"(addr));
}
__device__ __forceinline__ void ldsm4t(uint32_t& r0, uint32_t& r1, uint32_t& r2, uint32_t& r3,
                                       uint32_t addr) {
    asm volatile("ldmatrix.sync.aligned.m8n8.x4.trans.shared.b16 {%0,%1,%2,%3}, [%4];"
                 : "=r"(r0), "=r"(r1), "=r"(r2), "=r"(r3) : "r"(addr));
}
__device__ __forceinline__ void cp16(uint32_t dst, const void* src) {
    asm volatile("cp.async.cg.shared.global [%0], [%1], 16;" :: "r"(dst), "l"(src));
}

// ---------------------------------------------------------------------------
// 1. CPE (3x3 depthwise + residual) fused with mean pool + fp16 emission
// ---------------------------------------------------------------------------
__global__ __launch_bounds__(256) void cpe_pool_kernel(const float* __restrict__ src,
                                                       const float* __restrict__ cw)
{
    const int bc = blockIdx.x;
    const int c  = bc & (Cc - 1);
    const float* sp = src     + (size_t)bc * HW;
    __half*      op = g_s_h   + (size_t)bc * HW;
    __half*      rp = g_src_h + (size_t)bc * HW;

    __shared__ float tile[64][65];
    __shared__ float wsh[9];
    __shared__ float rsum[8];

    const int t = threadIdx.x;
    if (t < 9) wsh[t] = cw[c * 9 + t];

    float psum = 0.f;
    #pragma unroll
    for (int j = 0; j < 4; j++) {
        const int idx = (t + j * 256) * 4;
        const int y = idx >> 6, x = idx & 63;
        float4 v = *(const float4*)&sp[idx];
        tile[y][x + 0] = v.x; tile[y][x + 1] = v.y;
        tile[y][x + 2] = v.z; tile[y][x + 3] = v.w;
        ((__half2*)rp)[idx / 2 + 0] = __floats2half2_rn(v.x, v.y);
        ((__half2*)rp)[idx / 2 + 1] = __floats2half2_rn(v.z, v.w);
        psum += (v.x + v.y) + (v.z + v.w);
    }
    #pragma unroll
    for (int s = 16; s; s >>= 1) psum += __shfl_xor_sync(~0u, psum, s);
    if ((t & 31) == 0) rsum[t >> 5] = psum;
    __syncthreads();
    if (t == 0) {
        float tot = 0.f;
        #pragma unroll
        for (int w = 0; w < 8; w++) tot += rsum[w];
        g_pool[bc] = tot * (1.0f / 4096.0f);
    }

    const float w00 = wsh[0], w01 = wsh[1], w02 = wsh[2];
    const float w10 = wsh[3], w11 = wsh[4], w12 = wsh[5];
    const float w20 = wsh[6], w21 = wsh[7], w22 = wsh[8];

    for (int idx = t; idx < HW; idx += 256) {
        const int y = idx >> 6, x = idx & 63;
        float acc = tile[y][x];
        const bool yt = (y > 0), yb = (y < 63), xl = (x > 0), xr = (x < 63);
        if (yt) {
            if (xl) acc += w00 * tile[y-1][x-1];
            acc += w01 * tile[y-1][x];
            if (xr) acc += w02 * tile[y-1][x+1];
        }
        if (xl) acc += w10 * tile[y][x-1];
        acc += w11 * tile[y][x];
        if (xr) acc += w12 * tile[y][x+1];
        if (yb) {
            if (xl) acc += w20 * tile[y+1][x-1];
            acc += w21 * tile[y+1][x];
            if (xr) acc += w22 * tile[y+1][x+1];
        }
        op[idx] = __float2half_rn(acc);
    }
}

// ---------------------------------------------------------------------------
// 2. Weight prep: wcat (ECA sigmoid inline) + qkv_w fp16 cast
// ---------------------------------------------------------------------------
#define WCAT_N (Bn * OUTC * 256)
__global__ void wprep_kernel(const float* __restrict__ ow, const float* __restrict__ qw,
                             const float* __restrict__ w3)
{
    const int idx = blockIdx.x * 256 + threadIdx.x;
    if (idx < WCAT_N) {
        const int b   = idx >> 17;
        const int rem = idx & 131071;
        const int cc  = rem & 255;
        float w = ow[rem];
        if (cc >= 128) {
            const int c  = cc - 128;
            const int pi = b * 128 + c;
            const float x0 = (c > 0)   ? g_pool[pi - 1] : 0.f;
            const float x1 = g_pool[pi];
            const float x2 = (c < 127) ? g_pool[pi + 1] : 0.f;
            const float z  = w3[0] * x0 + w3[1] * x1 + w3[2] * x2;
            w *= 1.0f / (1.0f + __expf(-z));
        }
        g_wcat_h[idx] = __float2half_rn(w);
    } else {
        const int j = idx - WCAT_N;
        if (j < 384 * 128) g_qkvw_h[j] = __float2half_rn(qw[j]);
    }
}

// ---------------------------------------------------------------------------
// GEMM geometry shared constants (3-stage cp.async ring, 1 barrier/chunk)
// ---------------------------------------------------------------------------
#define GSMEM 56832
#define ASTG  10240
#define BOFF  30720
#define BSTG  8704

// ---------------------------------------------------------------------------
// 3. QKV GEMM (fp16 accumulators): qkv[b](384x4096) = qkv_w(384x128) @ s[b]
// ---------------------------------------------------------------------------
__global__ __launch_bounds__(256, 3) void gemm_qkv_tc()
{
    constexpr int KTOT = 128, NCH = 4;
    const __half* A  = g_qkvw_h;
    const __half* B0 = g_s_h   + (size_t)blockIdx.z * Cc * HW;
    __half*       C  = g_qkv_h + (size_t)blockIdx.z * 3 * Cc * HW;

    extern __shared__ char dsm[];
    const int n0 = blockIdx.x * 128;
    const int m0 = blockIdx.y * 128;

    const int t = threadIdx.x;
    const int wid = t >> 5, lane = t & 31;
    const int lq = lane >> 2, lr = lane & 3;
    const int wm = (wid >> 2) * 64, wn = (wid & 3) * 32;

    uint32_t acc[4][4][2];
    #pragma unroll
    for (int i = 0; i < 4; i++)
        #pragma unroll
        for (int j = 0; j < 4; j++) { acc[i][j][0] = 0u; acc[i][j][1] = 0u; }

    const int am = t >> 1, akoff = (t & 1) * 16;
    const int bk = t >> 3, bnoff = (t & 7) * 8;
    const uint32_t dsb = (uint32_t)__cvta_generic_to_shared(dsm);

    auto loadA = [&](int stg, int c) {
        const __half* s = A + (size_t)(m0 + am) * KTOT + c * 32 + akoff;
        uint32_t d = dsb + stg * ASTG + (am * 40 + akoff) * 2;
        cp16(d, s); cp16(d + 16, s + 8);
    };
    auto loadB = [&](int stg, int c) {
        const __half* bp = B0 + (size_t)(c * 32 + bk) * HW;
        uint32_t d = dsb + BOFF + stg * BSTG + (bk * 136 + bnoff) * 2;
        cp16(d,       bp + n0 + bnoff);
        cp16(d + 128, bp + n0 + bnoff + 64);
    };

    const int aLaneRow = lane & 15, aLaneCol = (lane >> 4) * 8;
    const int bLaneK   = (lane & 7) + ((lane >> 3) & 1) * 8;
    const int bLaneN   = (lane >> 4) * 8;

    loadA(0, 0); loadB(0, 0);
    asm volatile("cp.async.commit_group;");
    loadA(1, 1); loadB(1, 1);
    asm volatile("cp.async.commit_group;");

    int stg = 0;
    #pragma unroll
    for (int c = 0; c < NCH; c++) {
        asm volatile("cp.async.wait_group 1;" ::: "memory");
        __syncthreads();

        if (c + 2 < NCH) {
            const int ps = (stg + 2 >= 3) ? stg - 1 : stg + 2;
            loadA(ps, c + 2); loadB(ps, c + 2);
        }
        asm volatile("cp.async.commit_group;");

        const uint32_t asb = dsb + stg * ASTG;
        const uint32_t bsb = dsb + BOFF + stg * BSTG;

        #pragma unroll
        for (int s2 = 0; s2 < 32; s2 += 16) {
            uint32_t af[4][4], bf[4][2];
            #pragma unroll
            for (int mi = 0; mi < 4; mi++) {
                const uint32_t addr = asb +
                    (uint32_t)(((wm + mi * 16 + aLaneRow) * 40 + s2 + aLaneCol) * 2);
                ldsm4(af[mi][0], af[mi][1], af[mi][2], af[mi][3], addr);
            }
            #pragma unroll
            for (int p = 0; p < 2; p++) {
                const uint32_t addr = bsb +
                    (uint32_t)(((s2 + bLaneK) * 136 + wn + p * 16 + bLaneN) * 2);
                ldsm4t(bf[2*p][0], bf[2*p][1], bf[2*p+1][0], bf[2*p+1][1], addr);
            }
            #pragma unroll
            for (int mi = 0; mi < 4; mi++)
                #pragma unroll
                for (int ni = 0; ni < 4; ni++)
                    mma16h(acc[mi][ni], af[mi], bf[ni]);
        }
        stg = (stg + 1 == 3) ? 0 : stg + 1;
    }

    #pragma unroll
    for (int mi = 0; mi < 4; mi++) {
        #pragma unroll
        for (int ni = 0; ni < 4; ni++) {
            const int row = m0 + wm + mi * 16 + lq;
            const int col = n0 + wn + ni * 8 + lr * 2;
            *(uint32_t*)&C[(size_t)row * HW + col]       = acc[mi][ni][0];
            *(uint32_t*)&C[(size_t)(row + 8) * HW + col] = acc[mi][ni][1];
        }
    }
}

// ---------------------------------------------------------------------------
// 6. out[b] (512x4096) = wcat[b] (512x256) @ [r1[b]; src[b]]  fp32 accum
// ---------------------------------------------------------------------------
__global__ __launch_bounds__(256, 2) void gemm_out_tc(float* __restrict__ out)
{
    constexpr int KTOT = 256, NCH = 8;
    const int b = blockIdx.z;
    const __half* A  = g_wcat_h + (size_t)b * OUTC * 256;
    const __half* B0 = g_r1_h   + (size_t)b * Cc * HW;
    const __half* B1 = g_src_h  + (size_t)b * Cc * HW;
    float*        C  = out      + (size_t)b * OUTC * HW;

    extern __shared__ char dsm[];
    const int n0 = blockIdx.x * 128;
    const int m0 = blockIdx.y * 128;

    const int t = threadIdx.x;
    const int wid = t >> 5, lane = t & 31;
    const int lq = lane >> 2, lr = lane & 3;
    const int wm = (wid >> 2) * 64, wn = (wid & 3) * 32;

    float acc[4][4][4];
    #pragma unroll
    for (int i = 0; i < 4; i++)
        #pragma unroll
        for (int j = 0; j < 4; j++)
            #pragma unroll
            for (int r = 0; r < 4; r++) acc[i][j][r] = 0.f;

    const int am = t >> 1, akoff = (t & 1) * 16;
    const int bk = t >> 3, bnoff = (t & 7) * 8;
    const uint32_t dsb = (uint32_t)__cvta_generic_to_shared(dsm);

    auto loadA = [&](int stg, int c) {
        const __half* s = A + (size_t)(m0 + am) * KTOT + c * 32 + akoff;
        uint32_t d = dsb + stg * ASTG + (am * 40 + akoff) * 2;
        cp16(d, s); cp16(d + 16, s + 8);
    };
    auto loadB = [&](int stg, int c) {
        const int kg = c * 32 + bk;
        const __half* bp = (kg < 128) ? B0 + (size_t)kg * HW
                                      : B1 + (size_t)(kg - 128) * HW;
        uint32_t d = dsb + BOFF + stg * BSTG + (bk * 136 + bnoff) * 2;
        cp16(d,       bp + n0 + bnoff);
        cp16(d + 128, bp + n0 + bnoff + 64);
    };

    const int aLaneRow = lane & 15, aLaneCol = (lane >> 4) * 8;
    const int bLaneK   = (lane & 7) + ((lane >> 3) & 1) * 8;
    const int bLaneN   = (lane >> 4) * 8;

    loadA(0, 0); loadB(0, 0);
    asm volatile("cp.async.commit_group;");
    loadA(1, 1); loadB(1, 1);
    asm volatile("cp.async.commit_group;");

    int stg = 0;
    #pragma unroll
    for (int c = 0; c < NCH; c++) {
        asm volatile("cp.async.wait_group 1;" ::: "memory");
        __syncthreads();

        if (c + 2 < NCH) {
            const int ps = (stg + 2 >= 3) ? stg - 1 : stg + 2;
            loadA(ps, c + 2); loadB(ps, c + 2);
        }
        asm volatile("cp.async.commit_group;");

        const uint32_t asb = dsb + stg * ASTG;
        const uint32_t bsb = dsb + BOFF + stg * BSTG;

        #pragma unroll
        for (int s2 = 0; s2 < 32; s2 += 16) {
            uint32_t af[4][4], bf[4][2];
            #pragma unroll
            for (int mi = 0; mi < 4; mi++) {
                const uint32_t addr = asb +
                    (uint32_t)(((wm + mi * 16 + aLaneRow) * 40 + s2 + aLaneCol) * 2);
                ldsm4(af[mi][0], af[mi][1], af[mi][2], af[mi][3], addr);
            }
            #pragma unroll
            for (int p = 0; p < 2; p++) {
                const uint32_t addr = bsb +
                    (uint32_t)(((s2 + bLaneK) * 136 + wn + p * 16 + bLaneN) * 2);
                ldsm4t(bf[2*p][0], bf[2*p][1], bf[2*p+1][0], bf[2*p+1][1], addr);
            }
            #pragma unroll
            for (int mi = 0; mi < 4; mi++)
                #pragma unroll
                for (int ni = 0; ni < 4; ni++)
                    mma16(acc[mi][ni], af[mi], bf[ni]);
        }
        stg = (stg + 1 == 3) ? 0 : stg + 1;
    }

    #pragma unroll
    for (int mi = 0; mi < 4; mi++) {
        #pragma unroll
        for (int ni = 0; ni < 4; ni++) {
            const int row = m0 + wm + mi * 16 + lq;
            const int col = n0 + wn + ni * 8 + lr * 2;
            __stcs((float2*)&C[(size_t)row * HW + col],
                   make_float2(acc[mi][ni][0], acc[mi][ni][1]));
            __stcs((float2*)&C[(size_t)(row + 8) * HW + col],
                   make_float2(acc[mi][ni][2], acc[mi][ni][3]));
        }
    }
}

// ---------------------------------------------------------------------------
// 4. Lambda partials (no max-subtraction; k ~ N(0,1), exp safe)  fp16 input
// ---------------------------------------------------------------------------
__global__ __launch_bounds__(256) void lambda_part_kernel()
{
    const int bx = blockIdx.x;
    const int bh = bx >> 2, ch = bx & 3;
    const int b = bh >> 3, h = bh & 7;
    const __half* kb = g_qkv_h + ((size_t)b * 384 + 128 + h * 16) * HW;
    const __half* vb = g_qkv_h + ((size_t)b * 384 + 256 + h * 16) * HW;

    __shared__ float kf[16][260];
    __shared__ float vv[16][260];
    __shared__ float red[256];

    const int t = threadIdx.x;
    const int ii = t >> 4, oo = t & 15;
    float acc = 0.f, ksum = 0.f;

    const int nbeg = ch * 1024;
    for (int n0 = nbeg; n0 < nbeg + 1024; n0 += 256) {
        #pragma unroll
        for (int l = 0; l < 2; l++) {
            const int f = t + l * 256;
            const int r = f >> 5, cc = (f & 31) * 8;
            uint4 kraw = *(const uint4*)&kb[(size_t)r * HW + n0 + cc];
            uint4 vraw = *(const uint4*)&vb[(size_t)r * HW + n0 + cc];
            const __half2* kh = (const __half2*)&kraw;
            const __half2* vh = (const __half2*)&vraw;
            #pragma unroll
            for (int u = 0; u < 4; u++) {
                float2 kx = __half22float2(kh[u]);
                float2 vx = __half22float2(vh[u]);
                kf[r][cc + u * 2 + 0] = __expf(kx.x);
                kf[r][cc + u * 2 + 1] = __expf(kx.y);
                vv[r][cc + u * 2 + 0] = vx.x;
                vv[r][cc + u * 2 + 1] = vx.y;
            }
        }
        __syncthreads();
        const float* kr = kf[ii];
        const float* vr = vv[oo];
        #pragma unroll
        for (int c = 0; c < 256; c += 4) {
            float4 a  = *(const float4*)&kr[c];
            float4 v4 = *(const float4*)&vr[c];
            acc = fmaf(a.x, v4.x, acc);
            acc = fmaf(a.y, v4.y, acc);
            acc = fmaf(a.z, v4.z, acc);
            acc = fmaf(a.w, v4.w, acc);
        }
        const float* ks = &kf[ii][oo * 16];
        #pragma unroll
        for (int c = 0; c < 16; c += 4) {
            float4 a = *(const float4*)&ks[c];
            ksum += (a.x + a.y) + (a.z + a.w);
        }
        __syncthreads();
    }
    g_lpart[ch][bh * 256 + t] = acc;
    red[t] = ksum;
    __syncthreads();
    if (oo == 0) {
        float s = 0.f;
        #pragma unroll
        for (int j = 0; j < 16; j++) s += red[ii * 16 + j];
        g_kps[ch][bh * 16 + ii] = s;
    }
}

// ---------------------------------------------------------------------------
// 5. result1 = content_output + q * position_lambda (fp16 in/out)
// ---------------------------------------------------------------------------
__global__ __launch_bounds__(256) void result1_kernel(const float* __restrict__ relpos)
{
    const int bh = blockIdx.z;
    const int b = bh >> 3, h = bh & 7;
    const int x0 = blockIdx.x * 16, y0 = blockIdx.y * 16;
    const __half* qb = g_qkv_h + ((size_t)b * 384 +       h * 16) * HW;
    const __half* vb = g_qkv_h + ((size_t)b * 384 + 256 + h * 16) * HW;

    __shared__ float vs[16][20][20];
    __shared__ float ls[16][16];
    __shared__ float rp[16][25];
    __shared__ float sinv[16];

    const int t = threadIdx.x;

    float p = 0.f;
    #pragma unroll
    for (int chn = 0; chn < 4; chn++) p += g_lpart[chn][bh * 256 + t];
    if (t < 16) {
        float s = 0.f;
        #pragma unroll
        for (int chn = 0; chn < 4; chn++) s += g_kps[chn][bh * 16 + t];
        sinv[t] = 0.25f / s;           // 0.25 = HD^-0.5
    }

    for (int idx = t; idx < 400; idx += 256) rp[idx / 25][idx % 25] = relpos[idx];
    for (int idx = t; idx < 16 * 400; idx += 256) {
        const int o = idx / 400, rem = idx % 400;
        const int yy = rem / 20, xx = rem % 20;
        const int gy = y0 + yy - 2, gx = x0 + xx - 2;
        float val = 0.f;
        if ((unsigned)gy < 64u && (unsigned)gx < 64u)
            val = __half2float(vb[(size_t)o * HW + gy * 64 + gx]);
        vs[o][yy][xx] = val;
    }
    __syncthreads();
    ls[t >> 4][t & 15] = p * sinv[t >> 4];
    __syncthreads();

    const int tx = t & 15, ty = t >> 4;
    const int n  = (y0 + ty) * 64 + (x0 + tx);

    float qreg[16];
    #pragma unroll
    for (int i = 0; i < 16; i++) qreg[i] = __half2float(qb[(size_t)i * HW + n]);

    #pragma unroll
    for (int o = 0; o < 16; o++) {
        float pos = 0.f;
        #pragma unroll
        for (int dy = 0; dy < 5; dy++)
            #pragma unroll
            for (int dx = 0; dx < 5; dx++)
                pos = fmaf(rp[o][dy * 5 + dx], vs[o][ty + dy][tx + dx], pos);
        float cont = 0.f;
        #pragma unroll
        for (int i = 0; i < 16; i++) cont = fmaf(qreg[i], ls[i][o], cont);
        g_r1_h[((size_t)bh * 16 + o) * HW + n] = __float2half_rn(cont + qreg[o] * pos);
    }
}

// ---------------------------------------------------------------------------
extern "C" void kernel_launch(void* const* d_in, const int* in_sizes, int n_in,
                              void* d_out, int out_size)
{
    const float* src      = (const float*)d_in[0];   // (16,128,64,64)
    const float* cpe_w    = (const float*)d_in[1];   // (128,1,3,3)
    const float* qkv_w    = (const float*)d_in[2];   // (384,128)
    const float* rel_pos  = (const float*)d_in[3];   // (16,5,5)
    const float* conv1d_w = (const float*)d_in[4];   // (3,)
    const float* out_w    = (const float*)d_in[5];   // (512,256)
    float* out = (float*)d_out;

    static bool attr_done = false;
    if (!attr_done) {
        cudaFuncSetAttribute(gemm_qkv_tc, cudaFuncAttributeMaxDynamicSharedMemorySize, GSMEM);
        cudaFuncSetAttribute(gemm_out_tc, cudaFuncAttributeMaxDynamicSharedMemorySize, GSMEM);
        attr_done = true;
    }

    cpe_pool_kernel<<<Bn * Cc, 256>>>(src, cpe_w);
    wprep_kernel<<<(WCAT_N + 384 * 128 + 255) / 256, 256>>>(out_w, qkv_w, conv1d_w);
    gemm_qkv_tc<<<dim3(32, 3, Bn), 256, GSMEM>>>();
    lambda_part_kernel<<<Bn * NHh * 4, 256>>>();
    result1_kernel<<<dim3(4, 4, Bn * NHh), 256>>>(rel_pos);
    gemm_out_tc<<<dim3(32, 4, Bn), 256, GSMEM>>>(out);
}

// round 13
// speedup vs baseline: 1.7026x; 1.7026x over previous
#include <cuda_runtime.h>
#include <cuda_bf16.h>
#include <cuda_fp16.h>
#include <cstdint>

// ---------------------------------------------------------------------------
// MHConvAttention  (B=16, C=128, H=W=64, NH=8, HD=16, WIN=5, OUT=512)
// Round 13: revert GEMMs to round-11 config; lambda via m16n8k16 tensor cores
// ---------------------------------------------------------------------------
#define Bn   16
#define Cc   128
#define NHh  8
#define HDd  16
#define HW   4096
#define OUTC 512

__device__ __half g_s_h  [(size_t)Bn * Cc * HW];         // CPE output (fp16)
__device__ __half g_src_h[(size_t)Bn * Cc * HW];         // src (fp16)
__device__ __half g_r1_h [(size_t)Bn * Cc * HW];         // result1 (fp16)
__device__ __half g_qkv_h[(size_t)Bn * 3 * Cc * HW];     // q|k|v (fp16)
__device__ float  g_pool [Bn * Cc];
__device__ __half g_wcat_h[(size_t)Bn * OUTC * 256];     // [W1 | W2*ca(b)] fp16
__device__ __half g_qkvw_h[384 * 128];                   // qkv_w fp16
__device__ float  g_lam  [Bn * NHh * 256];               // normalized lambda

// ---------------------------------------------------------------------------
// helpers
// ---------------------------------------------------------------------------
__device__ __forceinline__ void mma16(float* c, const uint32_t* a, const uint32_t* b) {
    asm volatile(
        "mma.sync.aligned.m16n8k16.row.col.f32.f16.f16.f32 "
        "{%0,%1,%2,%3},{%4,%5,%6,%7},{%8,%9},{%0,%1,%2,%3};"
        : "+f"(c[0]), "+f"(c[1]), "+f"(c[2]), "+f"(c[3])
        : "r"(a[0]), "r"(a[1]), "r"(a[2]), "r"(a[3]), "r"(b[0]), "r"(b[1]));
}
__device__ __forceinline__ void ldsm4(uint32_t& r0, uint32_t& r1, uint32_t& r2, uint32_t& r3,
                                      uint32_t addr) {
    asm volatile("ldmatrix.sync.aligned.m8n8.x4.shared.b16 {%0,%1,%2,%3}, [%4];"
                 : "=r"(r0), "=r"(r1), "=r"(r2), "=r"(r3) : "r"(addr));
}
__device__ __forceinline__ void ldsm4t(uint32_t& r0, uint32_t& r1, uint32_t& r2, uint32_t& r3,
                                       uint32_t addr) {
    asm volatile("ldmatrix.sync.aligned.m8n8.x4.trans.shared.b16 {%0,%1,%2,%3}, [%4];"
                 : "=r"(r0), "=r"(r1), "=r"(r2), "=r"(r3) : "r"(addr));
}
__device__ __forceinline__ void cp16(uint32_t dst, const void* src) {
    asm volatile("cp.async.cg.shared.global [%0], [%1], 16;" :: "r"(dst), "l"(src));
}

// ---------------------------------------------------------------------------
// 1. CPE (3x3 depthwise + residual) fused with mean pool + fp16 emission
// ---------------------------------------------------------------------------
__global__ __launch_bounds__(256) void cpe_pool_kernel(const float* __restrict__ src,
                                                       const float* __restrict__ cw)
{
    const int bc = blockIdx.x;
    const int c  = bc & (Cc - 1);
    const float* sp = src     + (size_t)bc * HW;
    __half*      op = g_s_h   + (size_t)bc * HW;
    __half*      rp = g_src_h + (size_t)bc * HW;

    __shared__ float tile[64][65];
    __shared__ float wsh[9];
    __shared__ float rsum[8];

    const int t = threadIdx.x;
    if (t < 9) wsh[t] = cw[c * 9 + t];

    float psum = 0.f;
    #pragma unroll
    for (int j = 0; j < 4; j++) {
        const int idx = (t + j * 256) * 4;
        const int y = idx >> 6, x = idx & 63;
        float4 v = *(const float4*)&sp[idx];
        tile[y][x + 0] = v.x; tile[y][x + 1] = v.y;
        tile[y][x + 2] = v.z; tile[y][x + 3] = v.w;
        ((__half2*)rp)[idx / 2 + 0] = __floats2half2_rn(v.x, v.y);
        ((__half2*)rp)[idx / 2 + 1] = __floats2half2_rn(v.z, v.w);
        psum += (v.x + v.y) + (v.z + v.w);
    }
    #pragma unroll
    for (int s = 16; s; s >>= 1) psum += __shfl_xor_sync(~0u, psum, s);
    if ((t & 31) == 0) rsum[t >> 5] = psum;
    __syncthreads();
    if (t == 0) {
        float tot = 0.f;
        #pragma unroll
        for (int w = 0; w < 8; w++) tot += rsum[w];
        g_pool[bc] = tot * (1.0f / 4096.0f);
    }

    const float w00 = wsh[0], w01 = wsh[1], w02 = wsh[2];
    const float w10 = wsh[3], w11 = wsh[4], w12 = wsh[5];
    const float w20 = wsh[6], w21 = wsh[7], w22 = wsh[8];

    for (int idx = t; idx < HW; idx += 256) {
        const int y = idx >> 6, x = idx & 63;
        float acc = tile[y][x];
        const bool yt = (y > 0), yb = (y < 63), xl = (x > 0), xr = (x < 63);
        if (yt) {
            if (xl) acc += w00 * tile[y-1][x-1];
            acc += w01 * tile[y-1][x];
            if (xr) acc += w02 * tile[y-1][x+1];
        }
        if (xl) acc += w10 * tile[y][x-1];
        acc += w11 * tile[y][x];
        if (xr) acc += w12 * tile[y][x+1];
        if (yb) {
            if (xl) acc += w20 * tile[y+1][x-1];
            acc += w21 * tile[y+1][x];
            if (xr) acc += w22 * tile[y+1][x+1];
        }
        op[idx] = __float2half_rn(acc);
    }
}

// ---------------------------------------------------------------------------
// 2. Weight prep: wcat (ECA sigmoid inline) + qkv_w fp16 cast
// ---------------------------------------------------------------------------
#define WCAT_N (Bn * OUTC * 256)
__global__ void wprep_kernel(const float* __restrict__ ow, const float* __restrict__ qw,
                             const float* __restrict__ w3)
{
    const int idx = blockIdx.x * 256 + threadIdx.x;
    if (idx < WCAT_N) {
        const int b   = idx >> 17;
        const int rem = idx & 131071;
        const int cc  = rem & 255;
        float w = ow[rem];
        if (cc >= 128) {
            const int c  = cc - 128;
            const int pi = b * 128 + c;
            const float x0 = (c > 0)   ? g_pool[pi - 1] : 0.f;
            const float x1 = g_pool[pi];
            const float x2 = (c < 127) ? g_pool[pi + 1] : 0.f;
            const float z  = w3[0] * x0 + w3[1] * x1 + w3[2] * x2;
            w *= 1.0f / (1.0f + __expf(-z));
        }
        g_wcat_h[idx] = __float2half_rn(w);
    } else {
        const int j = idx - WCAT_N;
        if (j < 384 * 128) g_qkvw_h[j] = __float2half_rn(qw[j]);
    }
}

// ---------------------------------------------------------------------------
// fp16 tensor-core GEMM body (round-11 config: fp32 accum, 2 CTAs/SM)
// ---------------------------------------------------------------------------
#define GSMEM 56832
#define ASTG  10240
#define BOFF  30720
#define BSTG  8704

template<int KTOT, typename OutT>
__device__ __forceinline__ void gemm_body_h(const __half* __restrict__ A,
                                            const __half* __restrict__ B0,
                                            const __half* __restrict__ B1,
                                            OutT* __restrict__ C)
{
    constexpr int NCH = KTOT / 32;
    extern __shared__ char dsm[];
    const int n0 = blockIdx.x * 128;
    const int m0 = blockIdx.y * 128;

    const int t = threadIdx.x;
    const int wid = t >> 5, lane = t & 31;
    const int lq = lane >> 2, lr = lane & 3;
    const int wm = (wid >> 2) * 64, wn = (wid & 3) * 32;

    float acc[4][4][4];
    #pragma unroll
    for (int i = 0; i < 4; i++)
        #pragma unroll
        for (int j = 0; j < 4; j++)
            #pragma unroll
            for (int r = 0; r < 4; r++) acc[i][j][r] = 0.f;

    const int am = t >> 1, akoff = (t & 1) * 16;
    const int bk = t >> 3, bnoff = (t & 7) * 8;
    const uint32_t dsb = (uint32_t)__cvta_generic_to_shared(dsm);

    auto loadA = [&](int stg, int c) {
        const __half* s = A + (size_t)(m0 + am) * KTOT + c * 32 + akoff;
        uint32_t d = dsb + stg * ASTG + (am * 40 + akoff) * 2;
        cp16(d, s); cp16(d + 16, s + 8);
    };
    auto loadB = [&](int stg, int c) {
        const int kg = c * 32 + bk;
        const __half* bp = (KTOT == 128 || kg < 128)
                           ? B0 + (size_t)kg * HW
                           : B1 + (size_t)(kg - 128) * HW;
        uint32_t d = dsb + BOFF + stg * BSTG + (bk * 136 + bnoff) * 2;
        cp16(d,       bp + n0 + bnoff);
        cp16(d + 128, bp + n0 + bnoff + 64);
    };

    const int aLaneRow = lane & 15, aLaneCol = (lane >> 4) * 8;
    const int bLaneK   = (lane & 7) + ((lane >> 3) & 1) * 8;
    const int bLaneN   = (lane >> 4) * 8;

    loadA(0, 0); loadB(0, 0);
    asm volatile("cp.async.commit_group;");
    if (NCH > 1) { loadA(1, 1); loadB(1, 1); }
    asm volatile("cp.async.commit_group;");

    int stg = 0;
    #pragma unroll
    for (int c = 0; c < NCH; c++) {
        asm volatile("cp.async.wait_group 1;" ::: "memory");
        __syncthreads();

        if (c + 2 < NCH) {
            const int ps = (stg + 2 >= 3) ? stg - 1 : stg + 2;
            loadA(ps, c + 2); loadB(ps, c + 2);
        }
        asm volatile("cp.async.commit_group;");

        const uint32_t asb = dsb + stg * ASTG;
        const uint32_t bsb = dsb + BOFF + stg * BSTG;

        #pragma unroll
        for (int s2 = 0; s2 < 32; s2 += 16) {
            uint32_t af[4][4], bf[4][2];
            #pragma unroll
            for (int mi = 0; mi < 4; mi++) {
                const uint32_t addr = asb +
                    (uint32_t)(((wm + mi * 16 + aLaneRow) * 40 + s2 + aLaneCol) * 2);
                ldsm4(af[mi][0], af[mi][1], af[mi][2], af[mi][3], addr);
            }
            #pragma unroll
            for (int p = 0; p < 2; p++) {
                const uint32_t addr = bsb +
                    (uint32_t)(((s2 + bLaneK) * 136 + wn + p * 16 + bLaneN) * 2);
                ldsm4t(bf[2*p][0], bf[2*p][1], bf[2*p+1][0], bf[2*p+1][1], addr);
            }
            #pragma unroll
            for (int mi = 0; mi < 4; mi++)
                #pragma unroll
                for (int ni = 0; ni < 4; ni++)
                    mma16(acc[mi][ni], af[mi], bf[ni]);
        }
        stg = (stg + 1 == 3) ? 0 : stg + 1;
    }

    #pragma unroll
    for (int mi = 0; mi < 4; mi++) {
        #pragma unroll
        for (int ni = 0; ni < 4; ni++) {
            const int row = m0 + wm + mi * 16 + lq;
            const int col = n0 + wn + ni * 8 + lr * 2;
            if constexpr (sizeof(OutT) == 2) {
                *(__half2*)&C[(size_t)row * HW + col] =
                    __floats2half2_rn(acc[mi][ni][0], acc[mi][ni][1]);
                *(__half2*)&C[(size_t)(row + 8) * HW + col] =
                    __floats2half2_rn(acc[mi][ni][2], acc[mi][ni][3]);
            } else {
                __stcs((float2*)&C[(size_t)row * HW + col],
                       make_float2(acc[mi][ni][0], acc[mi][ni][1]));
                __stcs((float2*)&C[(size_t)(row + 8) * HW + col],
                       make_float2(acc[mi][ni][2], acc[mi][ni][3]));
            }
        }
    }
}

// 3. QKV GEMM:  qkv[b] (384x4096) = qkv_w (384x128) @ s[b]  (fp16 out)
__global__ __launch_bounds__(256, 2) void gemm_qkv_tc()
{
    const int b = blockIdx.z;
    gemm_body_h<128, __half>(g_qkvw_h, g_s_h + (size_t)b * Cc * HW, nullptr,
                             g_qkv_h + (size_t)b * 3 * Cc * HW);
}

// 6. out[b] (512x4096) = wcat[b] (512x256) @ [r1[b]; src[b]]  (fp32 out)
__global__ __launch_bounds__(256, 2) void gemm_out_tc(float* __restrict__ out)
{
    const int b = blockIdx.z;
    gemm_body_h<256, float>(g_wcat_h + (size_t)b * OUTC * 256,
                            g_r1_h   + (size_t)b * Cc * HW,
                            g_src_h  + (size_t)b * Cc * HW,
                            out      + (size_t)b * OUTC * HW);
}

// ---------------------------------------------------------------------------
// 4. Lambda via tensor cores: lam[bh] = 0.25 * diag(1/ksum) * exp(k) @ v^T
//    1 block per bh; 8 warps each own a 512-col K-slice; 16x16 fp32 accum.
// ---------------------------------------------------------------------------
__global__ __launch_bounds__(256) void lambda_mma_kernel()
{
    const int bh = blockIdx.x;
    const int b = bh >> 3, h = bh & 7;
    const __half* kb = g_qkv_h + ((size_t)b * 384 + 128 + h * 16) * HW;
    const __half* vb = g_qkv_h + ((size_t)b * 384 + 256 + h * 16) * HW;

    __shared__ __half ks[16][520];
    __shared__ __half vs[16][520];
    __shared__ float racc[8][16][16];
    __shared__ float rsum[8][16];

    const int t = threadIdx.x, wid = t >> 5, lane = t & 31;
    const int lq = lane >> 2, lr = lane & 3;

    float acc[2][4] = {};
    float se0 = 0.f, se1 = 0.f;      // exp row-sums for rows lq, lq+8

    const int aRow = lane & 15, aCol = (lane >> 4) * 8;
    const int bRow = (lane & 7) + ((lane >> 3) & 1) * 8;
    const int bCol = (lane >> 4) * 8;

    const uint32_t ksb = (uint32_t)__cvta_generic_to_shared(&ks[0][0]);
    const uint32_t vsb = (uint32_t)__cvta_generic_to_shared(&vs[0][0]);
    const int w0 = wid * 64;

    for (int tile = 0; tile < 8; tile++) {
        const int nbase = tile * 512;
        #pragma unroll
        for (int j = 0; j < 4; j++) {
            const int s = t + j * 256;               // 0..1023
            const int r = s >> 6, ccol = (s & 63) * 8;
            cp16(ksb + (r * 520 + ccol) * 2, kb + (size_t)r * HW + nbase + ccol);
            cp16(vsb + (r * 520 + ccol) * 2, vb + (size_t)r * HW + nbase + ccol);
        }
        asm volatile("cp.async.commit_group;");
        asm volatile("cp.async.wait_group 0;" ::: "memory");
        __syncthreads();

        #pragma unroll
        for (int kk = 0; kk < 64; kk += 16) {
            uint32_t a[4], bq[4];
            ldsm4(a[0], a[1], a[2], a[3], ksb + (aRow * 520 + w0 + kk + aCol) * 2);
            ldsm4(bq[0], bq[1], bq[2], bq[3], vsb + (bRow * 520 + w0 + kk + bCol) * 2);
            #pragma unroll
            for (int r2 = 0; r2 < 4; r2++) {
                float2 f = __half22float2(*(__half2*)&a[r2]);
                f.x = __expf(f.x); f.y = __expf(f.y);
                if ((r2 & 1) == 0) se0 += f.x + f.y; else se1 += f.x + f.y;
                *(__half2*)&a[r2] = __floats2half2_rn(f.x, f.y);
            }
            uint32_t bg0[2] = { bq[0], bq[2] };
            uint32_t bg1[2] = { bq[1], bq[3] };
            mma16(acc[0], a, bg0);
            mma16(acc[1], a, bg1);
        }
        __syncthreads();
    }

    // reduce exp row-sums across the 4 lanes sharing lq
    se0 += __shfl_xor_sync(~0u, se0, 1); se0 += __shfl_xor_sync(~0u, se0, 2);
    se1 += __shfl_xor_sync(~0u, se1, 1); se1 += __shfl_xor_sync(~0u, se1, 2);
    if (lr == 0) { rsum[wid][lq] = se0; rsum[wid][lq + 8] = se1; }

    #pragma unroll
    for (int g = 0; g < 2; g++) {
        racc[wid][lq    ][g * 8 + lr * 2    ] = acc[g][0];
        racc[wid][lq    ][g * 8 + lr * 2 + 1] = acc[g][1];
        racc[wid][lq + 8][g * 8 + lr * 2    ] = acc[g][2];
        racc[wid][lq + 8][g * 8 + lr * 2 + 1] = acc[g][3];
    }
    __syncthreads();

    const int i = t >> 4, o = t & 15;
    float s = 0.f, ksum = 0.f;
    #pragma unroll
    for (int w = 0; w < 8; w++) { s += racc[w][i][o]; ksum += rsum[w][i]; }
    g_lam[bh * 256 + i * 16 + o] = 0.25f * s / ksum;      // 0.25 = HD^-0.5
}

// ---------------------------------------------------------------------------
// 5. result1 = content_output + q * position_lambda (fp16 in/out)
// ---------------------------------------------------------------------------
__global__ __launch_bounds__(256) void result1_kernel(const float* __restrict__ relpos)
{
    const int bh = blockIdx.z;
    const int b = bh >> 3, h = bh & 7;
    const int x0 = blockIdx.x * 16, y0 = blockIdx.y * 16;
    const __half* qb = g_qkv_h + ((size_t)b * 384 +       h * 16) * HW;
    const __half* vb = g_qkv_h + ((size_t)b * 384 + 256 + h * 16) * HW;

    __shared__ float vs[16][20][20];
    __shared__ float ls[16][16];
    __shared__ float rp[16][25];

    const int t = threadIdx.x;

    ls[t >> 4][t & 15] = g_lam[bh * 256 + t];
    for (int idx = t; idx < 400; idx += 256) rp[idx / 25][idx % 25] = relpos[idx];
    for (int idx = t; idx < 16 * 400; idx += 256) {
        const int o = idx / 400, rem = idx % 400;
        const int yy = rem / 20, xx = rem % 20;
        const int gy = y0 + yy - 2, gx = x0 + xx - 2;
        float val = 0.f;
        if ((unsigned)gy < 64u && (unsigned)gx < 64u)
            val = __half2float(vb[(size_t)o * HW + gy * 64 + gx]);
        vs[o][yy][xx] = val;
    }
    __syncthreads();

    const int tx = t & 15, ty = t >> 4;
    const int n  = (y0 + ty) * 64 + (x0 + tx);

    float qreg[16];
    #pragma unroll
    for (int i = 0; i < 16; i++) qreg[i] = __half2float(qb[(size_t)i * HW + n]);

    #pragma unroll
    for (int o = 0; o < 16; o++) {
        float pos = 0.f;
        #pragma unroll
        for (int dy = 0; dy < 5; dy++)
            #pragma unroll
            for (int dx = 0; dx < 5; dx++)
                pos = fmaf(rp[o][dy * 5 + dx], vs[o][ty + dy][tx + dx], pos);
        float cont = 0.f;
        #pragma unroll
        for (int i = 0; i < 16; i++) cont = fmaf(qreg[i], ls[i][o], cont);
        g_r1_h[((size_t)bh * 16 + o) * HW + n] = __float2half_rn(cont + qreg[o] * pos);
    }
}

// ---------------------------------------------------------------------------
extern "C" void kernel_launch(void* const* d_in, const int* in_sizes, int n_in,
                              void* d_out, int out_size)
{
    const float* src      = (const float*)d_in[0];   // (16,128,64,64)
    const float* cpe_w    = (const float*)d_in[1];   // (128,1,3,3)
    const float* qkv_w    = (const float*)d_in[2];   // (384,128)
    const float* rel_pos  = (const float*)d_in[3];   // (16,5,5)
    const float* conv1d_w = (const float*)d_in[4];   // (3,)
    const float* out_w    = (const float*)d_in[5];   // (512,256)
    float* out = (float*)d_out;

    static bool attr_done = false;
    if (!attr_done) {
        cudaFuncSetAttribute(gemm_qkv_tc, cudaFuncAttributeMaxDynamicSharedMemorySize, GSMEM);
        cudaFuncSetAttribute(gemm_out_tc, cudaFuncAttributeMaxDynamicSharedMemorySize, GSMEM);
        attr_done = true;
    }

    cpe_pool_kernel<<<Bn * Cc, 256>>>(src, cpe_w);
    wprep_kernel<<<(WCAT_N + 384 * 128 + 255) / 256, 256>>>(out_w, qkv_w, conv1d_w);
    gemm_qkv_tc<<<dim3(32, 3, Bn), 256, GSMEM>>>();
    lambda_mma_kernel<<<Bn * NHh, 256>>>();
    result1_kernel<<<dim3(4, 4, Bn * NHh), 256>>>(rel_pos);
    gemm_out_tc<<<dim3(32, 4, Bn), 256, GSMEM>>>(out);
}

// round 14
// speedup vs baseline: 1.7806x; 1.0458x over previous
#include <cuda_runtime.h>
#include <cuda_bf16.h>
#include <cuda_fp16.h>
#include <cstdint>

// ---------------------------------------------------------------------------
// MHConvAttention  (B=16, C=128, H=W=64, NH=8, HD=16, WIN=5, OUT=512)
// Round 14: 64x128 GEMM tiles @ 3 CTAs/SM (32x32 warp tiles); lambda split-K
// ---------------------------------------------------------------------------
#define Bn   16
#define Cc   128
#define NHh  8
#define HDd  16
#define HW   4096
#define OUTC 512

__device__ __half g_s_h  [(size_t)Bn * Cc * HW];         // CPE output (fp16)
__device__ __half g_src_h[(size_t)Bn * Cc * HW];         // src (fp16)
__device__ __half g_r1_h [(size_t)Bn * Cc * HW];         // result1 (fp16)
__device__ __half g_qkv_h[(size_t)Bn * 3 * Cc * HW];     // q|k|v (fp16)
__device__ float  g_pool [Bn * Cc];
__device__ __half g_wcat_h[(size_t)Bn * OUTC * 256];     // [W1 | W2*ca(b)] fp16
__device__ __half g_qkvw_h[384 * 128];                   // qkv_w fp16
__device__ float  g_lam2 [2][Bn * NHh * 256];            // unnormalized partials
__device__ float  g_ksum2[2][Bn * NHh * 16];             // exp row-sum partials

// ---------------------------------------------------------------------------
// helpers
// ---------------------------------------------------------------------------
__device__ __forceinline__ void mma16(float* c, const uint32_t* a, const uint32_t* b) {
    asm volatile(
        "mma.sync.aligned.m16n8k16.row.col.f32.f16.f16.f32 "
        "{%0,%1,%2,%3},{%4,%5,%6,%7},{%8,%9},{%0,%1,%2,%3};"
        : "+f"(c[0]), "+f"(c[1]), "+f"(c[2]), "+f"(c[3])
        : "r"(a[0]), "r"(a[1]), "r"(a[2]), "r"(a[3]), "r"(b[0]), "r"(b[1]));
}
__device__ __forceinline__ void ldsm4(uint32_t& r0, uint32_t& r1, uint32_t& r2, uint32_t& r3,
                                      uint32_t addr) {
    asm volatile("ldmatrix.sync.aligned.m8n8.x4.shared.b16 {%0,%1,%2,%3}, [%4];"
                 : "=r"(r0), "=r"(r1), "=r"(r2), "=r"(r3) : "r"(addr));
}
__device__ __forceinline__ void ldsm4t(uint32_t& r0, uint32_t& r1, uint32_t& r2, uint32_t& r3,
                                       uint32_t addr) {
    asm volatile("ldmatrix.sync.aligned.m8n8.x4.trans.shared.b16 {%0,%1,%2,%3}, [%4];"
                 : "=r"(r0), "=r"(r1), "=r"(r2), "=r"(r3) : "r"(addr));
}
__device__ __forceinline__ void cp16(uint32_t dst, const void* src) {
    asm volatile("cp.async.cg.shared.global [%0], [%1], 16;" :: "r"(dst), "l"(src));
}

// ---------------------------------------------------------------------------
// 1. CPE (3x3 depthwise + residual) fused with mean pool + fp16 emission
// ---------------------------------------------------------------------------
__global__ __launch_bounds__(256) void cpe_pool_kernel(const float* __restrict__ src,
                                                       const float* __restrict__ cw)
{
    const int bc = blockIdx.x;
    const int c  = bc & (Cc - 1);
    const float* sp = src     + (size_t)bc * HW;
    __half*      op = g_s_h   + (size_t)bc * HW;
    __half*      rp = g_src_h + (size_t)bc * HW;

    __shared__ float tile[64][65];
    __shared__ float wsh[9];
    __shared__ float rsum[8];

    const int t = threadIdx.x;
    if (t < 9) wsh[t] = cw[c * 9 + t];

    float psum = 0.f;
    #pragma unroll
    for (int j = 0; j < 4; j++) {
        const int idx = (t + j * 256) * 4;
        const int y = idx >> 6, x = idx & 63;
        float4 v = *(const float4*)&sp[idx];
        tile[y][x + 0] = v.x; tile[y][x + 1] = v.y;
        tile[y][x + 2] = v.z; tile[y][x + 3] = v.w;
        ((__half2*)rp)[idx / 2 + 0] = __floats2half2_rn(v.x, v.y);
        ((__half2*)rp)[idx / 2 + 1] = __floats2half2_rn(v.z, v.w);
        psum += (v.x + v.y) + (v.z + v.w);
    }
    #pragma unroll
    for (int s = 16; s; s >>= 1) psum += __shfl_xor_sync(~0u, psum, s);
    if ((t & 31) == 0) rsum[t >> 5] = psum;
    __syncthreads();
    if (t == 0) {
        float tot = 0.f;
        #pragma unroll
        for (int w = 0; w < 8; w++) tot += rsum[w];
        g_pool[bc] = tot * (1.0f / 4096.0f);
    }

    const float w00 = wsh[0], w01 = wsh[1], w02 = wsh[2];
    const float w10 = wsh[3], w11 = wsh[4], w12 = wsh[5];
    const float w20 = wsh[6], w21 = wsh[7], w22 = wsh[8];

    for (int idx = t; idx < HW; idx += 256) {
        const int y = idx >> 6, x = idx & 63;
        float acc = tile[y][x];
        const bool yt = (y > 0), yb = (y < 63), xl = (x > 0), xr = (x < 63);
        if (yt) {
            if (xl) acc += w00 * tile[y-1][x-1];
            acc += w01 * tile[y-1][x];
            if (xr) acc += w02 * tile[y-1][x+1];
        }
        if (xl) acc += w10 * tile[y][x-1];
        acc += w11 * tile[y][x];
        if (xr) acc += w12 * tile[y][x+1];
        if (yb) {
            if (xl) acc += w20 * tile[y+1][x-1];
            acc += w21 * tile[y+1][x];
            if (xr) acc += w22 * tile[y+1][x+1];
        }
        op[idx] = __float2half_rn(acc);
    }
}

// ---------------------------------------------------------------------------
// 2. Weight prep: wcat (ECA sigmoid inline) + qkv_w fp16 cast
// ---------------------------------------------------------------------------
#define WCAT_N (Bn * OUTC * 256)
__global__ void wprep_kernel(const float* __restrict__ ow, const float* __restrict__ qw,
                             const float* __restrict__ w3)
{
    const int idx = blockIdx.x * 256 + threadIdx.x;
    if (idx < WCAT_N) {
        const int b   = idx >> 17;
        const int rem = idx & 131071;
        const int cc  = rem & 255;
        float w = ow[rem];
        if (cc >= 128) {
            const int c  = cc - 128;
            const int pi = b * 128 + c;
            const float x0 = (c > 0)   ? g_pool[pi - 1] : 0.f;
            const float x1 = g_pool[pi];
            const float x2 = (c < 127) ? g_pool[pi + 1] : 0.f;
            const float z  = w3[0] * x0 + w3[1] * x1 + w3[2] * x2;
            w *= 1.0f / (1.0f + __expf(-z));
        }
        g_wcat_h[idx] = __float2half_rn(w);
    } else {
        const int j = idx - WCAT_N;
        if (j < 384 * 128) g_qkvw_h[j] = __float2half_rn(qw[j]);
    }
}

// ---------------------------------------------------------------------------
// fp16 tensor-core GEMM body: C(64x128 tile) = A(64xKTOT) @ B(KTOTx4096)
// 256 threads = 8 warps (2x4), warp tile 32x32, mma m16n8k16, chunk K=32.
// 3-stage cp.async ring, 1 barrier/chunk, 3 CTAs/SM.
// ---------------------------------------------------------------------------
#define ASTG  5120
#define BOFF  15360
#define BSTG  8704
#define GSMEM (BOFF + 3 * BSTG)     // 41472

template<int KTOT, typename OutT>
__device__ __forceinline__ void gemm_body_h(const __half* __restrict__ A,
                                            const __half* __restrict__ B0,
                                            const __half* __restrict__ B1,
                                            OutT* __restrict__ C)
{
    constexpr int NCH = KTOT / 32;
    extern __shared__ char dsm[];
    const int n0 = blockIdx.x * 128;
    const int m0 = blockIdx.y * 64;

    const int t = threadIdx.x;
    const int wid = t >> 5, lane = t & 31;
    const int lq = lane >> 2, lr = lane & 3;
    const int wm = (wid >> 2) * 32, wn = (wid & 3) * 32;

    float acc[2][4][4];
    #pragma unroll
    for (int i = 0; i < 2; i++)
        #pragma unroll
        for (int j = 0; j < 4; j++)
            #pragma unroll
            for (int r = 0; r < 4; r++) acc[i][j][r] = 0.f;

    const int am = t >> 2, akoff = (t & 3) * 8;    // 64 rows x 32 halves/chunk
    const int bk = t >> 3, bnoff = (t & 7) * 8;
    const uint32_t dsb = (uint32_t)__cvta_generic_to_shared(dsm);

    auto loadA = [&](int stg, int c) {
        const __half* s = A + (size_t)(m0 + am) * KTOT + c * 32 + akoff;
        cp16(dsb + stg * ASTG + (am * 40 + akoff) * 2, s);
    };
    auto loadB = [&](int stg, int c) {
        const int kg = c * 32 + bk;
        const __half* bp = (KTOT == 128 || kg < 128)
                           ? B0 + (size_t)kg * HW
                           : B1 + (size_t)(kg - 128) * HW;
        uint32_t d = dsb + BOFF + stg * BSTG + (bk * 136 + bnoff) * 2;
        cp16(d,       bp + n0 + bnoff);
        cp16(d + 128, bp + n0 + bnoff + 64);
    };

    const int aLaneRow = lane & 15, aLaneCol = (lane >> 4) * 8;
    const int bLaneK   = (lane & 7) + ((lane >> 3) & 1) * 8;
    const int bLaneN   = (lane >> 4) * 8;

    loadA(0, 0); loadB(0, 0);
    asm volatile("cp.async.commit_group;");
    if (NCH > 1) { loadA(1, 1); loadB(1, 1); }
    asm volatile("cp.async.commit_group;");

    int stg = 0;
    #pragma unroll
    for (int c = 0; c < NCH; c++) {
        asm volatile("cp.async.wait_group 1;" ::: "memory");
        __syncthreads();

        if (c + 2 < NCH) {
            const int ps = (stg + 2 >= 3) ? stg - 1 : stg + 2;
            loadA(ps, c + 2); loadB(ps, c + 2);
        }
        asm volatile("cp.async.commit_group;");

        const uint32_t asb = dsb + stg * ASTG;
        const uint32_t bsb = dsb + BOFF + stg * BSTG;

        #pragma unroll
        for (int s2 = 0; s2 < 32; s2 += 16) {
            uint32_t af[2][4], bf[4][2];
            #pragma unroll
            for (int mi = 0; mi < 2; mi++) {
                const uint32_t addr = asb +
                    (uint32_t)(((wm + mi * 16 + aLaneRow) * 40 + s2 + aLaneCol) * 2);
                ldsm4(af[mi][0], af[mi][1], af[mi][2], af[mi][3], addr);
            }
            #pragma unroll
            for (int p = 0; p < 2; p++) {
                const uint32_t addr = bsb +
                    (uint32_t)(((s2 + bLaneK) * 136 + wn + p * 16 + bLaneN) * 2);
                ldsm4t(bf[2*p][0], bf[2*p][1], bf[2*p+1][0], bf[2*p+1][1], addr);
            }
            #pragma unroll
            for (int mi = 0; mi < 2; mi++)
                #pragma unroll
                for (int ni = 0; ni < 4; ni++)
                    mma16(acc[mi][ni], af[mi], bf[ni]);
        }
        stg = (stg + 1 == 3) ? 0 : stg + 1;
    }

    #pragma unroll
    for (int mi = 0; mi < 2; mi++) {
        #pragma unroll
        for (int ni = 0; ni < 4; ni++) {
            const int row = m0 + wm + mi * 16 + lq;
            const int col = n0 + wn + ni * 8 + lr * 2;
            if constexpr (sizeof(OutT) == 2) {
                *(__half2*)&C[(size_t)row * HW + col] =
                    __floats2half2_rn(acc[mi][ni][0], acc[mi][ni][1]);
                *(__half2*)&C[(size_t)(row + 8) * HW + col] =
                    __floats2half2_rn(acc[mi][ni][2], acc[mi][ni][3]);
            } else {
                __stcs((float2*)&C[(size_t)row * HW + col],
                       make_float2(acc[mi][ni][0], acc[mi][ni][1]));
                __stcs((float2*)&C[(size_t)(row + 8) * HW + col],
                       make_float2(acc[mi][ni][2], acc[mi][ni][3]));
            }
        }
    }
}

// 3. QKV GEMM:  qkv[b] (384x4096) = qkv_w (384x128) @ s[b]  (fp16 out)
__global__ __launch_bounds__(256, 3) void gemm_qkv_tc()
{
    const int b = blockIdx.z;
    gemm_body_h<128, __half>(g_qkvw_h, g_s_h + (size_t)b * Cc * HW, nullptr,
                             g_qkv_h + (size_t)b * 3 * Cc * HW);
}

// 6. out[b] (512x4096) = wcat[b] (512x256) @ [r1[b]; src[b]]  (fp32 out)
__global__ __launch_bounds__(256, 3) void gemm_out_tc(float* __restrict__ out)
{
    const int b = blockIdx.z;
    gemm_body_h<256, float>(g_wcat_h + (size_t)b * OUTC * 256,
                            g_r1_h   + (size_t)b * Cc * HW,
                            g_src_h  + (size_t)b * Cc * HW,
                            out      + (size_t)b * OUTC * HW);
}

// ---------------------------------------------------------------------------
// 4. Lambda via tensor cores, split-K x2:
//    g_lam2[half][bh] += exp(k_half) @ v_half^T ; g_ksum2 = exp row sums.
// ---------------------------------------------------------------------------
__global__ __launch_bounds__(256) void lambda_mma_kernel()
{
    const int bx = blockIdx.x;
    const int bh = bx >> 1, half = bx & 1;
    const int b = bh >> 3, h = bh & 7;
    const __half* kb = g_qkv_h + ((size_t)b * 384 + 128 + h * 16) * HW;
    const __half* vb = g_qkv_h + ((size_t)b * 384 + 256 + h * 16) * HW;

    __shared__ __half ks[16][520];
    __shared__ __half vs[16][520];
    __shared__ float racc[8][16][16];
    __shared__ float rsum[8][16];

    const int t = threadIdx.x, wid = t >> 5, lane = t & 31;
    const int lq = lane >> 2, lr = lane & 3;

    float acc[2][4] = {};
    float se0 = 0.f, se1 = 0.f;

    const int aRow = lane & 15, aCol = (lane >> 4) * 8;
    const int bRow = (lane & 7) + ((lane >> 3) & 1) * 8;
    const int bCol = (lane >> 4) * 8;

    const uint32_t ksb = (uint32_t)__cvta_generic_to_shared(&ks[0][0]);
    const uint32_t vsb = (uint32_t)__cvta_generic_to_shared(&vs[0][0]);
    const int w0 = wid * 64;

    for (int tile = 0; tile < 4; tile++) {
        const int nbase = half * 2048 + tile * 512;
        #pragma unroll
        for (int j = 0; j < 4; j++) {
            const int s = t + j * 256;
            const int r = s >> 6, ccol = (s & 63) * 8;
            cp16(ksb + (r * 520 + ccol) * 2, kb + (size_t)r * HW + nbase + ccol);
            cp16(vsb + (r * 520 + ccol) * 2, vb + (size_t)r * HW + nbase + ccol);
        }
        asm volatile("cp.async.commit_group;");
        asm volatile("cp.async.wait_group 0;" ::: "memory");
        __syncthreads();

        #pragma unroll
        for (int kk = 0; kk < 64; kk += 16) {
            uint32_t a[4], bq[4];
            ldsm4(a[0], a[1], a[2], a[3], ksb + (aRow * 520 + w0 + kk + aCol) * 2);
            ldsm4(bq[0], bq[1], bq[2], bq[3], vsb + (bRow * 520 + w0 + kk + bCol) * 2);
            #pragma unroll
            for (int r2 = 0; r2 < 4; r2++) {
                float2 f = __half22float2(*(__half2*)&a[r2]);
                f.x = __expf(f.x); f.y = __expf(f.y);
                if ((r2 & 1) == 0) se0 += f.x + f.y; else se1 += f.x + f.y;
                *(__half2*)&a[r2] = __floats2half2_rn(f.x, f.y);
            }
            uint32_t bg0[2] = { bq[0], bq[2] };
            uint32_t bg1[2] = { bq[1], bq[3] };
            mma16(acc[0], a, bg0);
            mma16(acc[1], a, bg1);
        }
        __syncthreads();
    }

    se0 += __shfl_xor_sync(~0u, se0, 1); se0 += __shfl_xor_sync(~0u, se0, 2);
    se1 += __shfl_xor_sync(~0u, se1, 1); se1 += __shfl_xor_sync(~0u, se1, 2);
    if (lr == 0) { rsum[wid][lq] = se0; rsum[wid][lq + 8] = se1; }

    #pragma unroll
    for (int g = 0; g < 2; g++) {
        racc[wid][lq    ][g * 8 + lr * 2    ] = acc[g][0];
        racc[wid][lq    ][g * 8 + lr * 2 + 1] = acc[g][1];
        racc[wid][lq + 8][g * 8 + lr * 2    ] = acc[g][2];
        racc[wid][lq + 8][g * 8 + lr * 2 + 1] = acc[g][3];
    }
    __syncthreads();

    const int i = t >> 4, o = t & 15;
    float s = 0.f, ksum = 0.f;
    #pragma unroll
    for (int w = 0; w < 8; w++) { s += racc[w][i][o]; ksum += rsum[w][i]; }
    g_lam2[half][bh * 256 + i * 16 + o] = s;
    if (o == 0) g_ksum2[half][bh * 16 + i] = ksum;
}

// ---------------------------------------------------------------------------
// 5. result1 = content_output + q * position_lambda (reduces lambda halves)
// ---------------------------------------------------------------------------
__global__ __launch_bounds__(256) void result1_kernel(const float* __restrict__ relpos)
{
    const int bh = blockIdx.z;
    const int b = bh >> 3, h = bh & 7;
    const int x0 = blockIdx.x * 16, y0 = blockIdx.y * 16;
    const __half* qb = g_qkv_h + ((size_t)b * 384 +       h * 16) * HW;
    const __half* vb = g_qkv_h + ((size_t)b * 384 + 256 + h * 16) * HW;

    __shared__ float vs[16][20][20];
    __shared__ float ls[16][16];
    __shared__ float rp[16][25];
    __shared__ float sinv[16];

    const int t = threadIdx.x;

    const float lm = g_lam2[0][bh * 256 + t] + g_lam2[1][bh * 256 + t];
    if (t < 16)
        sinv[t] = 0.25f / (g_ksum2[0][bh * 16 + t] + g_ksum2[1][bh * 16 + t]);

    for (int idx = t; idx < 400; idx += 256) rp[idx / 25][idx % 25] = relpos[idx];
    for (int idx = t; idx < 16 * 400; idx += 256) {
        const int o = idx / 400, rem = idx % 400;
        const int yy = rem / 20, xx = rem % 20;
        const int gy = y0 + yy - 2, gx = x0 + xx - 2;
        float val = 0.f;
        if ((unsigned)gy < 64u && (unsigned)gx < 64u)
            val = __half2float(vb[(size_t)o * HW + gy * 64 + gx]);
        vs[o][yy][xx] = val;
    }
    __syncthreads();
    ls[t >> 4][t & 15] = lm * sinv[t >> 4];
    __syncthreads();

    const int tx = t & 15, ty = t >> 4;
    const int n  = (y0 + ty) * 64 + (x0 + tx);

    float qreg[16];
    #pragma unroll
    for (int i = 0; i < 16; i++) qreg[i] = __half2float(qb[(size_t)i * HW + n]);

    #pragma unroll
    for (int o = 0; o < 16; o++) {
        float pos = 0.f;
        #pragma unroll
        for (int dy = 0; dy < 5; dy++)
            #pragma unroll
            for (int dx = 0; dx < 5; dx++)
                pos = fmaf(rp[o][dy * 5 + dx], vs[o][ty + dy][tx + dx], pos);
        float cont = 0.f;
        #pragma unroll
        for (int i = 0; i < 16; i++) cont = fmaf(qreg[i], ls[i][o], cont);
        g_r1_h[((size_t)bh * 16 + o) * HW + n] = __float2half_rn(cont + qreg[o] * pos);
    }
}

// ---------------------------------------------------------------------------
extern "C" void kernel_launch(void* const* d_in, const int* in_sizes, int n_in,
                              void* d_out, int out_size)
{
    const float* src      = (const float*)d_in[0];   // (16,128,64,64)
    const float* cpe_w    = (const float*)d_in[1];   // (128,1,3,3)
    const float* qkv_w    = (const float*)d_in[2];   // (384,128)
    const float* rel_pos  = (const float*)d_in[3];   // (16,5,5)
    const float* conv1d_w = (const float*)d_in[4];   // (3,)
    const float* out_w    = (const float*)d_in[5];   // (512,256)
    float* out = (float*)d_out;

    static bool attr_done = false;
    if (!attr_done) {
        cudaFuncSetAttribute(gemm_qkv_tc, cudaFuncAttributeMaxDynamicSharedMemorySize, GSMEM);
        cudaFuncSetAttribute(gemm_out_tc, cudaFuncAttributeMaxDynamicSharedMemorySize, GSMEM);
        attr_done = true;
    }

    cpe_pool_kernel<<<Bn * Cc, 256>>>(src, cpe_w);
    wprep_kernel<<<(WCAT_N + 384 * 128 + 255) / 256, 256>>>(out_w, qkv_w, conv1d_w);
    gemm_qkv_tc<<<dim3(32, 6, Bn), 256, GSMEM>>>();
    lambda_mma_kernel<<<Bn * NHh * 2, 256>>>();
    result1_kernel<<<dim3(4, 4, Bn * NHh), 256>>>(rel_pos);
    gemm_out_tc<<<dim3(32, 8, Bn), 256, GSMEM>>>(out);
}